// round 9
// baseline (speedup 1.0000x reference)
#include <cuda_runtime.h>
#include <cuda_bf16.h>
#include <stdint.h>

// Segment-max of per-row scalar projection.
//   r[n] = dot(feats[n,:32], W) + b ;  out[p] = max(0, max_{idx[n]==p} r[n])
//
// R8 profile: segmax @ 6.87 TB/s (86% HBM spec), DRAM=84%, pure streaming.
// This round: persistent grid-stride segmax (740 CTAs = 5/SM reg-limit) to
// remove 13 waves of CTA churn + per-block prologue; hoist invariants.

__device__ int g_idx_is32;   // 1 if idx stored as int32, 0 if int64

// ---------------------------------------------------------------------------
// Fused init: zero output (float4) + idx dtype detect (bounds-safe: reads
// only words < nrows, valid for both layouts; int64 values < 2^17 have all
// odd words zero; int32 odd words are idx values, ~never all zero).
// ---------------------------------------------------------------------------
__global__ void init_detect_kernel(float4* __restrict__ out4, int p4,
                                   const int* __restrict__ idx_words, int nrows,
                                   int nzb)
{
    if ((int)blockIdx.x < nzb) {
        int i = blockIdx.x * blockDim.x + threadIdx.x;
        if (i < p4) out4[i] = make_float4(0.f, 0.f, 0.f, 0.f);
    } else {
        if (threadIdx.x == 0) g_idx_is32 = 0;
        __syncthreads();
        int i = threadIdx.x;
        #pragma unroll
        for (int pass = 0; pass < 4; pass++, i += 256) {
            long long stride = (long long)nrows / 2048; if (stride < 1) stride = 1;
            long long k = ((long long)i * stride * 2) | 1;   // odd word index
            if (k < nrows && idx_words[k] != 0) { atomicOr(&g_idx_is32, 1); break; }
        }
    }
}

// ---------------------------------------------------------------------------
// Persistent segmax: each warp strides over 32-row tiles.
// 8 lanes/row; 8 fully-coalesced front-batched LDG.128 per tile (512B each);
// shfl_xor tree over 8-lane groups; no-return atomicMax on int bits.
// ---------------------------------------------------------------------------
__global__ __launch_bounds__(256) void segmax_kernel(
    const float4* __restrict__ feats,   // [N,8] float4
    const float*  __restrict__ W,       // [32]
    const float*  __restrict__ b,       // [1]
    const int*    __restrict__ idx_w,   // idx as 32-bit words
    float*        __restrict__ out,     // [P]
    int nrows, int nwarps_total)
{
    const int gwarp = (blockIdx.x * blockDim.x + threadIdx.x) >> 5;
    const int lane  = threadIdx.x & 31;

    const bool  is32 = (g_idx_is32 != 0);
    const float bias = b[0];
    const float4 wv  = ((const float4*)W)[lane & 7];   // lane's weight chunk

    const long long ntiles = ((long long)nrows + 31) >> 5;

    for (long long tile = gwarp; tile < ntiles; tile += nwarps_total) {
        const long long rowBase = tile << 5;

        // Coalesced idx prefetch: lane l -> seg of row rowBase+l
        long long ir = rowBase + lane;
        if (ir >= nrows) ir = nrows - 1;
        int myseg = is32 ? idx_w[ir] : idx_w[2 * ir];

        const float4* base4 = feats + rowBase * 8;

        if (rowBase + 32 <= nrows) {
            float4 v[8];
#pragma unroll
            for (int k = 0; k < 8; k++) v[k] = base4[k * 32 + lane];

#pragma unroll
            for (int k = 0; k < 8; k++) {
                float s = fmaf(v[k].x, wv.x,
                          fmaf(v[k].y, wv.y,
                          fmaf(v[k].z, wv.z, v[k].w * wv.w)));
                s += __shfl_xor_sync(0xffffffffu, s, 1);
                s += __shfl_xor_sync(0xffffffffu, s, 2);
                s += __shfl_xor_sync(0xffffffffu, s, 4);
                int rsel = k * 4 + (lane >> 3);
                int seg  = __shfl_sync(0xffffffffu, myseg, rsel);
                float r  = s + bias;
                if ((lane & 7) == 0 && r > 0.0f)
                    atomicMax((int*)out + seg, __float_as_int(r));
            }
        } else {
            // tail tile (at most one per grid pass)
            for (int k = 0; k < 8; k++) {
                long long row = rowBase + k * 4 + (lane >> 3);
                float4 v = make_float4(0.f, 0.f, 0.f, 0.f);
                if (row < nrows) v = base4[k * 32 + lane];
                float s = fmaf(v.x, wv.x, fmaf(v.y, wv.y, fmaf(v.z, wv.z, v.w * wv.w)));
                s += __shfl_xor_sync(0xffffffffu, s, 1);
                s += __shfl_xor_sync(0xffffffffu, s, 2);
                s += __shfl_xor_sync(0xffffffffu, s, 4);
                int rsel = k * 4 + (lane >> 3);
                int seg  = __shfl_sync(0xffffffffu, myseg, rsel);
                float r  = s + bias;
                if ((lane & 7) == 0 && r > 0.0f && row < nrows)
                    atomicMax((int*)out + seg, __float_as_int(r));
            }
        }
    }
}

// ---------------------------------------------------------------------------
extern "C" void kernel_launch(void* const* d_in, const int* in_sizes, int n_in,
                              void* d_out, int out_size)
{
    const float4* feats = (const float4*)d_in[0];
    const float*  W     = (const float*) d_in[1];
    const float*  b     = (const float*) d_in[2];
    const int*    idx_w = (const int*)   d_in[3];

    int nrows = in_sizes[0] / 32;   // N rows (feats element count / F)
    int P     = out_size;           // 100,000 (multiple of 4)

    float* out = (float*)d_out;

    int p4  = P / 4;
    int nzb = (p4 + 255) / 256;
    init_detect_kernel<<<nzb + 1, 256>>>((float4*)out, p4, idx_w, nrows, nzb);

    // Persistent: 5 blocks/SM (reg-limited occupancy) x 148 SMs
    int blocks = 740;
    int nwarps_total = blocks * (256 / 32);
    segmax_kernel<<<blocks, 256>>>(feats, W, b, idx_w, out, nrows, nwarps_total);
}

// round 11
// speedup vs baseline: 1.1981x; 1.1981x over previous
#include <cuda_runtime.h>
#include <cuda_bf16.h>
#include <stdint.h>

// Segment-max of per-row scalar projection.
//   r[n] = dot(feats[n,:32], W) + b ;  out[p] = max(0, max_{idx[n]==p} r[n])
//
// R9 finding: persistent grid-stride REGRESSED (63 regs, occ 42%, DRAM 67%)
// -- serial per-warp tiles starve HBM of outstanding loads. Reverted to the
// R8 structure: one 32-row tile per warp, 15625 CTAs, HW wave rotation.
// Tweak: __launch_bounds__(256,6) caps regs at 42 -> 6 blocks/SM (occ 62%).

__device__ int g_idx_is32;   // 1 if idx stored as int32, 0 if int64

// ---------------------------------------------------------------------------
// Fused init: zero output (float4) + idx dtype detect (bounds-safe: reads
// only words < nrows, valid for both layouts; int64 values < 2^17 have all
// odd words zero; int32 odd words are idx values, ~never all zero).
// ---------------------------------------------------------------------------
__global__ void init_detect_kernel(float4* __restrict__ out4, int p4,
                                   const int* __restrict__ idx_words, int nrows,
                                   int nzb)
{
    if ((int)blockIdx.x < nzb) {
        int i = blockIdx.x * blockDim.x + threadIdx.x;
        if (i < p4) out4[i] = make_float4(0.f, 0.f, 0.f, 0.f);
    } else {
        if (threadIdx.x == 0) g_idx_is32 = 0;
        __syncthreads();
        int i = threadIdx.x;
        #pragma unroll
        for (int pass = 0; pass < 4; pass++, i += 256) {
            long long stride = (long long)nrows / 2048; if (stride < 1) stride = 1;
            long long k = ((long long)i * stride * 2) | 1;   // odd word index
            if (k < nrows && idx_words[k] != 0) { atomicOr(&g_idx_is32, 1); break; }
        }
    }
}

// ---------------------------------------------------------------------------
// Main fused projection + segment max: one 32-row tile per warp.
// 8 lanes/row; 8 fully-coalesced front-batched LDG.128 (512B each, MLP=8);
// shfl_xor tree over 8-lane groups; no-return atomicMax on int bits.
// ---------------------------------------------------------------------------
__global__ __launch_bounds__(256, 6) void segmax_kernel(
    const float4* __restrict__ feats,   // [N,8] float4
    const float*  __restrict__ W,       // [32]
    const float*  __restrict__ b,       // [1]
    const int*    __restrict__ idx_w,   // idx as 32-bit words
    float*        __restrict__ out,     // [P]
    int nrows)
{
    int gwarp = (blockIdx.x * blockDim.x + threadIdx.x) >> 5;
    int lane  = threadIdx.x & 31;
    long long rowBase = (long long)gwarp * 32;
    if (rowBase >= nrows) return;

    const bool  is32 = (g_idx_is32 != 0);
    const float bias = b[0];
    const float4 wv  = ((const float4*)W)[lane & 7];   // lane's weight chunk

    // Coalesced idx prefetch: lane l holds seg of row rowBase+l
    long long ir = rowBase + lane;
    if (ir >= nrows) ir = nrows - 1;
    int myseg = is32 ? idx_w[ir] : idx_w[2 * ir];

    const float4* base4 = feats + rowBase * 8;

    if (rowBase + 32 <= nrows) {
        // ---- fast path: 8 fully-coalesced LDG.128, front-batched (MLP=8)
        float4 v[8];
#pragma unroll
        for (int k = 0; k < 8; k++) v[k] = base4[k * 32 + lane];

#pragma unroll
        for (int k = 0; k < 8; k++) {
            float s = fmaf(v[k].x, wv.x,
                      fmaf(v[k].y, wv.y,
                      fmaf(v[k].z, wv.z, v[k].w * wv.w)));
            s += __shfl_xor_sync(0xffffffffu, s, 1);
            s += __shfl_xor_sync(0xffffffffu, s, 2);
            s += __shfl_xor_sync(0xffffffffu, s, 4);
            int rsel = k * 4 + (lane >> 3);            // row within warp
            int seg  = __shfl_sync(0xffffffffu, myseg, rsel);
            float r  = s + bias;
            if ((lane & 7) == 0 && r > 0.0f)
                atomicMax((int*)out + seg, __float_as_int(r));
        }
    } else {
        // ---- tail path (rare): guard each row
        for (int k = 0; k < 8; k++) {
            long long row = rowBase + k * 4 + (lane >> 3);
            float4 v = make_float4(0.f, 0.f, 0.f, 0.f);
            if (row < nrows) v = base4[k * 32 + lane];
            float s = fmaf(v.x, wv.x, fmaf(v.y, wv.y, fmaf(v.z, wv.z, v.w * wv.w)));
            s += __shfl_xor_sync(0xffffffffu, s, 1);
            s += __shfl_xor_sync(0xffffffffu, s, 2);
            s += __shfl_xor_sync(0xffffffffu, s, 4);
            int rsel = k * 4 + (lane >> 3);
            int seg  = __shfl_sync(0xffffffffu, myseg, rsel);
            float r  = s + bias;
            if ((lane & 7) == 0 && r > 0.0f && row < nrows)
                atomicMax((int*)out + seg, __float_as_int(r));
        }
    }
}

// ---------------------------------------------------------------------------
extern "C" void kernel_launch(void* const* d_in, const int* in_sizes, int n_in,
                              void* d_out, int out_size)
{
    const float4* feats = (const float4*)d_in[0];
    const float*  W     = (const float*) d_in[1];
    const float*  b     = (const float*) d_in[2];
    const int*    idx_w = (const int*)   d_in[3];

    int nrows = in_sizes[0] / 32;   // N rows (feats element count / F)
    int P     = out_size;           // 100,000 (multiple of 4)

    float* out = (float*)d_out;

    int p4  = P / 4;
    int nzb = (p4 + 255) / 256;
    init_detect_kernel<<<nzb + 1, 256>>>((float4*)out, p4, idx_w, nrows, nzb);

    // one warp per 32 rows, 8 warps per block => 256 rows per block
    int blocks = (int)(((long long)nrows + 255) / 256);
    segmax_kernel<<<blocks, 256>>>(feats, W, b, idx_w, out, nrows);
}

// round 12
// speedup vs baseline: 1.2656x; 1.0563x over previous
#include <cuda_runtime.h>
#include <cuda_bf16.h>
#include <stdint.h>

// Segment-max of per-row scalar projection.
//   r[n] = dot(feats[n,:32], W) + b ;  out[p] = max(0, max_{idx[n]==p} r[n])
//
// R11 finding: __launch_bounds__(256,6) cut regs to 40, broke the 8-load
// front batch (DRAM 84->77%). Reverted to R8-exact (48 regs, occ 52%,
// 79.9us). Added: __ldcs streaming hints on feats/idx (touched once).

__device__ int g_idx_is32;   // 1 if idx stored as int32, 0 if int64

// ---------------------------------------------------------------------------
// Fused init: zero output (float4) + idx dtype detect (bounds-safe: reads
// only words < nrows, valid for both layouts; int64 values < 2^17 have all
// odd words zero; int32 odd words are idx values, ~never all zero).
// ---------------------------------------------------------------------------
__global__ void init_detect_kernel(float4* __restrict__ out4, int p4,
                                   const int* __restrict__ idx_words, int nrows,
                                   int nzb)
{
    if ((int)blockIdx.x < nzb) {
        int i = blockIdx.x * blockDim.x + threadIdx.x;
        if (i < p4) out4[i] = make_float4(0.f, 0.f, 0.f, 0.f);
    } else {
        if (threadIdx.x == 0) g_idx_is32 = 0;
        __syncthreads();
        int i = threadIdx.x;
        #pragma unroll
        for (int pass = 0; pass < 4; pass++, i += 256) {
            long long stride = (long long)nrows / 2048; if (stride < 1) stride = 1;
            long long k = ((long long)i * stride * 2) | 1;   // odd word index
            if (k < nrows && idx_words[k] != 0) { atomicOr(&g_idx_is32, 1); break; }
        }
    }
}

// ---------------------------------------------------------------------------
// Main fused projection + segment max: one 32-row tile per warp.
// 8 lanes/row; 8 fully-coalesced front-batched LDG.128 (512B each, MLP=8);
// shfl_xor tree over 8-lane groups; no-return atomicMax on int bits.
// ---------------------------------------------------------------------------
__global__ __launch_bounds__(256) void segmax_kernel(
    const float4* __restrict__ feats,   // [N,8] float4
    const float*  __restrict__ W,       // [32]
    const float*  __restrict__ b,       // [1]
    const int*    __restrict__ idx_w,   // idx as 32-bit words
    float*        __restrict__ out,     // [P]
    int nrows)
{
    int gwarp = (blockIdx.x * blockDim.x + threadIdx.x) >> 5;
    int lane  = threadIdx.x & 31;
    long long rowBase = (long long)gwarp * 32;
    if (rowBase >= nrows) return;

    const bool  is32 = (g_idx_is32 != 0);
    const float bias = b[0];
    const float4 wv  = ((const float4*)W)[lane & 7];   // lane's weight chunk

    // Coalesced idx prefetch (streaming): lane l holds seg of row rowBase+l
    long long ir = rowBase + lane;
    if (ir >= nrows) ir = nrows - 1;
    int myseg = is32 ? __ldcs(idx_w + ir) : __ldcs(idx_w + 2 * ir);

    const float4* base4 = feats + rowBase * 8;

    if (rowBase + 32 <= nrows) {
        // ---- fast path: 8 fully-coalesced LDG.128, front-batched (MLP=8)
        float4 v[8];
#pragma unroll
        for (int k = 0; k < 8; k++) v[k] = __ldcs(base4 + k * 32 + lane);

#pragma unroll
        for (int k = 0; k < 8; k++) {
            float s = fmaf(v[k].x, wv.x,
                      fmaf(v[k].y, wv.y,
                      fmaf(v[k].z, wv.z, v[k].w * wv.w)));
            s += __shfl_xor_sync(0xffffffffu, s, 1);
            s += __shfl_xor_sync(0xffffffffu, s, 2);
            s += __shfl_xor_sync(0xffffffffu, s, 4);
            int rsel = k * 4 + (lane >> 3);            // row within warp
            int seg  = __shfl_sync(0xffffffffu, myseg, rsel);
            float r  = s + bias;
            if ((lane & 7) == 0 && r > 0.0f)
                atomicMax((int*)out + seg, __float_as_int(r));
        }
    } else {
        // ---- tail path (rare): guard each row
        for (int k = 0; k < 8; k++) {
            long long row = rowBase + k * 4 + (lane >> 3);
            float4 v = make_float4(0.f, 0.f, 0.f, 0.f);
            if (row < nrows) v = __ldcs(base4 + k * 32 + lane);
            float s = fmaf(v.x, wv.x, fmaf(v.y, wv.y, fmaf(v.z, wv.z, v.w * wv.w)));
            s += __shfl_xor_sync(0xffffffffu, s, 1);
            s += __shfl_xor_sync(0xffffffffu, s, 2);
            s += __shfl_xor_sync(0xffffffffu, s, 4);
            int rsel = k * 4 + (lane >> 3);
            int seg  = __shfl_sync(0xffffffffu, myseg, rsel);
            float r  = s + bias;
            if ((lane & 7) == 0 && r > 0.0f && row < nrows)
                atomicMax((int*)out + seg, __float_as_int(r));
        }
    }
}

// ---------------------------------------------------------------------------
extern "C" void kernel_launch(void* const* d_in, const int* in_sizes, int n_in,
                              void* d_out, int out_size)
{
    const float4* feats = (const float4*)d_in[0];
    const float*  W     = (const float*) d_in[1];
    const float*  b     = (const float*) d_in[2];
    const int*    idx_w = (const int*)   d_in[3];

    int nrows = in_sizes[0] / 32;   // N rows (feats element count / F)
    int P     = out_size;           // 100,000 (multiple of 4)

    float* out = (float*)d_out;

    int p4  = P / 4;
    int nzb = (p4 + 255) / 256;
    init_detect_kernel<<<nzb + 1, 256>>>((float4*)out, p4, idx_w, nrows, nzb);

    // one warp per 32 rows, 8 warps per block => 256 rows per block
    int blocks = (int)(((long long)nrows + 255) / 256);
    segmax_kernel<<<blocks, 256>>>(feats, W, b, idx_w, out, nrows);
}